// round 6
// baseline (speedup 1.0000x reference)
#include <cuda_runtime.h>
#include <cuda_fp16.h>
#include <math.h>

// Problem constants
#define NB 64
#define NA 256
#define NROWS (NB*NA)          // 16384 (b,i) rows
#define AE 20                  // atomemb dim
#define DF 25                  // gaussian features
#define VW_COLS 45             // AE + DF

// Nearest-neighbor exp-table: 1537 node rows over [0,5], 20 outputs packed as
// 10 half2 words = 40 bytes/row (stride 10 words).
#define TBL 1536
#define TW 10
#define TBL_WORDS ((TBL+1)*TW)   // 15370 words = 61.5 KB

#define CTANH 2.885390081777926814f   // 2/ln2

typedef unsigned long long ULL;

// Device scratch (no allocations allowed)
__device__ unsigned d_tableh[TBL_WORDS];  // half2: E_o(d) = exp(2*g_o(d))
__device__ float d_ebf  [NROWS*AE];       // exp(2*base_o) per row, fp32
__device__ float d_cfeat[NROWS*AE];
__device__ float d_weff [AE];
__device__ float d_beff;
__device__ float d_erow [NROWS];

__device__ __forceinline__ float fast_tanh(float x) {
    float e;
    asm("ex2.approx.f32 %0, %1;" : "=f"(e) : "f"(x * CTANH));
    float r;
    asm("rcp.approx.f32 %0, %1;" : "=f"(r) : "f"(e + 1.0f));
    return fmaf(-2.0f, r, 1.0f);
}
__device__ __forceinline__ float rcpf(float x) {
    float r; asm("rcp.approx.f32 %0, %1;" : "=f"(r) : "f"(x)); return r;
}
__device__ __forceinline__ ULL pk(float lo, float hi) {
    ULL r; asm("mov.b64 %0, {%1, %2};" : "=l"(r) : "f"(lo), "f"(hi)); return r;
}
__device__ __forceinline__ float2 upk(ULL v) {
    float2 r; asm("mov.b64 {%0, %1}, %2;" : "=f"(r.x), "=f"(r.y) : "l"(v)); return r;
}
__device__ __forceinline__ ULL fma2(ULL a, ULL b, ULL c) {
    ULL d; asm("fma.rn.f32x2 %0, %1, %2, %3;" : "=l"(d) : "l"(a), "l"(b), "l"(c)); return d;
}

// ---------- prep: Weff = W2 @ W1, beff = W2@b1 + b2 ----------
__global__ void k_weff(const float* __restrict__ W1, const float* __restrict__ b1,
                       const float* __restrict__ W2, const float* __restrict__ b2) {
    int t = threadIdx.x;
    if (t < AE) {
        float s = 0.f;
        #pragma unroll
        for (int m = 0; m < 10; m++) s += W2[m] * W1[m*AE + t];
        d_weff[t] = s;
    }
    if (t == AE) {
        float s = b2[0];
        #pragma unroll
        for (int m = 0; m < 10; m++) s += W2[m] * b1[m];
        d_beff = s;
    }
}

// ---------- prep: E table (half2 pairs): exp(2 * g_o(d)) ----------
__global__ void k_table(const float* __restrict__ Vw) {
    int idx = blockIdx.x * blockDim.x + threadIdx.x;
    if (idx >= (TBL+1)*TW) return;
    int t = idx / TW;
    int w = idx - t*TW;
    float d = (float)t * (5.0f / (float)TBL);
    float g[2];
    #pragma unroll
    for (int p = 0; p < 2; p++) {
        int o = 2*w + p;
        float s = 0.f;
        #pragma unroll
        for (int k = 0; k < DF; k++) {
            float x = d - 0.2f * (float)k;
            s += Vw[o*VW_COLS + AE + k] * __expf(-2.0f * x * x);
        }
        g[p] = __expf(2.0f * s);
    }
    __half2 h = __floats2half2_rn(g[0], g[1]);
    d_tableh[t*TW + w] = *(unsigned*)&h;
}

// ---------- prep: cfeat and Eb = exp(2*(cfeat @ Vw1^T + Vb)) ----------
__global__ void k_rows(const int* __restrict__ z, const float* __restrict__ emb,
                       const float* __restrict__ Vw, const float* __restrict__ Vb) {
    int idx = blockIdx.x * blockDim.x + threadIdx.x;
    if (idx >= NROWS*AE) return;
    int row = idx / AE;
    int o   = idx - row*AE;
    int zi  = z[row];
    float m = (zi != 0) ? 1.f : 0.f;
    d_cfeat[idx] = m * emb[zi*AE + o];
    float b = Vb[o];
    #pragma unroll
    for (int f = 0; f < AE; f++)
        b = fmaf(m * emb[zi*AE + f], Vw[o*VW_COLS + f], b);
    d_ebf[idx] = __expf(2.0f * b);
}

// ---------- main: one warp per (b,i) row; parity-rotated LDS + f32x2 math ----
__global__ void __launch_bounds__(384, 2)
k_main(const float* __restrict__ dist, const int* __restrict__ z) {
    extern __shared__ unsigned tabw[];
    const int tid = threadIdx.x;
    for (int i = tid; i < TBL_WORDS; i += blockDim.x) tabw[i] = d_tableh[i];
    __syncthreads();

    const int lane = tid & 31;
    const int rot  = (lane & 1) * 5;   // word rotation: odd lanes shift by 5 (flips bank parity)
    const int nwarps = gridDim.x * (blockDim.x >> 5);
    int gw = blockIdx.x * (blockDim.x >> 5) + (tid >> 5);

    const ULL ONE2 = pk(1.0f, 1.0f);

    for (int row = gw; row < NROWS; row += nwarps) {
        // eb pairs, labeled by this lane's rotation: slot k <-> table word w(k)
        const float* ep = d_ebf + row*AE;
        ULL ebs[10], acc[10];
        #pragma unroll
        for (int k = 0; k < 10; k++) {
            int w = (k < 5) ? (k + rot) : (k - rot);
            float2 e = __ldg((const float2*)(ep + 2*w));
            ebs[k] = pk(e.x, e.y);
            acc[k] = pk(0.0f, 0.0f);
        }

        // lane handles j = lane*8 .. lane*8+7
        const float4* drow4 = (const float4*)(dist + (size_t)row * NA + lane * 8);
        float4 dv0 = __ldg(drow4);
        float4 dv1 = __ldg(drow4 + 1);
        float dv[8] = {dv0.x, dv0.y, dv0.z, dv0.w, dv1.x, dv1.y, dv1.z, dv1.w};

        #pragma unroll
        for (int jt = 0; jt < 8; jt++) {
            int ti = __float2int_rn(dv[jt] * ((float)TBL / 5.0f));
            const unsigned* bA = tabw + ti*TW + rot;   // words k+rot   (k<5)
            const unsigned* bB = bA - 2*rot;           // words k-rot   (k>=5)
            unsigned Ew[10];
            #pragma unroll
            for (int k = 0; k < 5;  k++) Ew[k] = bA[k];
            #pragma unroll
            for (int k = 5; k < 10; k++) Ew[k] = bB[k];
            #pragma unroll
            for (int k = 0; k < 10; k++) {
                float2 ef = __half22float2(*(const __half2*)&Ew[k]);
                ULL y2 = fma2(pk(ef.x, ef.y), ebs[k], ONE2);  // (y_lo, y_hi)
                float2 yf = upk(y2);
                float r = rcpf(yf.x * yf.y);                  // 1/(y_lo*y_hi)
                acc[k] = fma2(y2, pk(r, r), acc[k]);          // += (1/y_hi, 1/y_lo)
            }
        }

        // unpack accumulators: a[2k] = sum 1/y_hi(w), a[2k+1] = sum 1/y_lo(w)
        float a[20];
        #pragma unroll
        for (int k = 0; k < 10; k++) {
            float2 v = upk(acc[k]);
            a[2*k] = v.x; a[2*k+1] = v.y;
        }

        // step 1: xor-1 with compile-time slot remap (odd lanes rotated by 5 words)
        #pragma unroll
        for (int k = 0; k < 5; k++) {
            float t0x = __shfl_xor_sync(0xffffffffu, a[2*(k+5)  ], 1);
            float t0y = __shfl_xor_sync(0xffffffffu, a[2*(k+5)+1], 1);
            float t1x = __shfl_xor_sync(0xffffffffu, a[2*k  ], 1);
            float t1y = __shfl_xor_sync(0xffffffffu, a[2*k+1], 1);
            a[2*k  ]     += t0x;  a[2*k+1]     += t0y;
            a[2*(k+5)  ] += t1x;  a[2*(k+5)+1] += t1y;
        }
        // remaining butterfly (labels aligned now)
        #pragma unroll
        for (int off = 2; off <= 16; off <<= 1) {
            #pragma unroll
            for (int i = 0; i < 20; i++)
                a[i] += __shfl_xor_sync(0xffffffffu, a[i], off);
        }

        if (lane == 0) {   // lane 0: rot=0, slot k == word k == outputs (2k, 2k+1)
            float m = (z[row] != 0) ? 1.f : 0.f;
            float e = d_beff;
            const float* cf = d_cfeat + row*AE;
            #pragma unroll
            for (int k = 0; k < 10; k++) {
                // output 2k   <- a[2k+1] (sum 1/y_lo); output 2k+1 <- a[2k]
                float c0 = (cf[2*k  ] + fmaf(-2.0f, a[2*k+1], 256.0f)) * m;
                float c1 = (cf[2*k+1] + fmaf(-2.0f, a[2*k  ], 256.0f)) * m;
                e = fmaf(d_weff[2*k  ], fast_tanh(c0), e);
                e = fmaf(d_weff[2*k+1], fast_tanh(c1), e);
            }
            d_erow[row] = e;
        }
    }
}

// ---------- final: out[b] = sum_i e[b,i] ----------
__global__ void k_out(float* __restrict__ out) {
    __shared__ float sh[8];
    int b = blockIdx.x, t = threadIdx.x;
    float v = d_erow[b*NA + t];
    #pragma unroll
    for (int off = 16; off; off >>= 1) v += __shfl_xor_sync(0xffffffffu, v, off);
    if ((t & 31) == 0) sh[t >> 5] = v;
    __syncthreads();
    if (t == 0) {
        float s = 0.f;
        #pragma unroll
        for (int i = 0; i < 8; i++) s += sh[i];
        out[b] = s;
    }
}

extern "C" void kernel_launch(void* const* d_in, const int* in_sizes, int n_in,
                              void* d_out, int out_size) {
    const int*   z    = (const int*)  d_in[0];
    const float* dist = (const float*)d_in[1];
    const float* emb  = (const float*)d_in[2];
    const float* Vw   = (const float*)d_in[3];
    const float* Vb   = (const float*)d_in[4];
    const float* W1   = (const float*)d_in[5];
    const float* b1   = (const float*)d_in[6];
    const float* W2   = (const float*)d_in[7];
    const float* b2   = (const float*)d_in[8];
    float* out = (float*)d_out;
    (void)in_sizes; (void)n_in; (void)out_size;

    cudaFuncSetAttribute(k_main, cudaFuncAttributeMaxDynamicSharedMemorySize,
                         TBL_WORDS * 4);

    k_weff <<<1, 64>>>(W1, b1, W2, b2);
    k_table<<<((TBL+1)*TW + 127)/128, 128>>>(Vw);
    k_rows <<<(NROWS*AE + 127)/128, 128>>>(z, emb, Vw, Vb);
    k_main <<<296, 384, TBL_WORDS * 4>>>(dist, z);
    k_out  <<<NB, 256>>>(out);
}